// round 11
// baseline (speedup 1.0000x reference)
#include <cuda_runtime.h>
#include <cuda_bf16.h>
#include <math.h>
#include <cstdint>

// NeRFRenderer null-scattering marcher (max_depths=1): all tot replicas of a
// ray are identical -> single per-ray eval: ray-sphere hit, equirect env-map
// bilinear sample, attenuate.
//
// inputs: d_in[0] rays_o f32[N,3], d_in[1] rays_d f32[N,3],
//         d_in[2] env_map f32[1,3,16,32], d_in[3..4] step counts (cancel).
// output: f32 [N,3]
//
// R10: 128 CTAs x 64 threads, 2 rays/thread (ILP=2). Halves env-preload
// traffic and CTA count (single clean wave on 148 SMs); two independent
// ray chains per thread hide LDG/MUFU/LDS latency in-thread. Env staged in
// smem via register float4s (measured best vs cp.async in R9).

#define ENV_H 16
#define ENV_W 32
#define ENV_HW (ENV_H * ENV_W)
#define ENV_ELEMS (3 * ENV_HW)              // 1536 floats = 384 float4
#define SIGMA_MAJORANT 0.1f
#define PI_F 3.14159265358979323846f
#define THREADS 64
#define RAYS_PER_THREAD 2
#define F4_PER_THREAD (ENV_ELEMS / 4 / THREADS)   // 6

// fast acos, max err ~6.7e-5 rad
__device__ __forceinline__ float acos_fast(float x) {
    float ax = fabsf(x);
    float r = sqrtf(1.0f - ax) *
              (1.5707288f + ax * (-0.2121144f + ax * (0.0742610f + ax * (-0.0187293f))));
    return x < 0.0f ? (PI_F - r) : r;
}

// atan on [0,1], max err ~1e-5 rad
__device__ __forceinline__ float atan_poly(float a) {
    float s = a * a;
    return a * (0.9998660f + s * (-0.3302995f + s * (0.1801410f +
               s * (-0.0851330f + s * 0.0208351f))));
}

// fast atan2 (returns 0 at (0,0), matching nan_to_num in the reference)
__device__ __forceinline__ float atan2_fast(float y, float x) {
    float ay = fabsf(y), ax = fabsf(x);
    bool swap = ay > ax;
    float num = swap ? ax : ay;
    float den = swap ? ay : ax;
    den = fmaxf(den, 1e-30f);
    float r = atan_poly(__fdividef(num, den));
    if (swap) r = 1.57079632679f - r;
    if (x < 0.0f) r = PI_F - r;
    return y < 0.0f ? -r : r;
}

struct RayOut {
    float v0, v1, v2;
};

// everything up to (but not including) the smem gather for one ray
struct RayPre {
    float t_hit;
    bool  valid;
    int   x0, y0;
    float wx1, wy1;
};

__device__ __forceinline__ RayPre ray_pre(const float* __restrict__ rays_o,
                                          const float* __restrict__ rays_d,
                                          int i)
{
    const float ox = rays_o[3 * i + 0];
    const float oy = rays_o[3 * i + 1];
    const float oz = rays_o[3 * i + 2];
    const float dx = rays_d[3 * i + 0];
    const float dy = rays_d[3 * i + 1];
    const float dz = rays_d[3 * i + 2];

    const float a = dx * dx + dy * dy + dz * dz;
    const float c = ox * ox + oy * oy + oz * oz - 1.0f;
    const float b = 2.0f * (ox * dx + oy * dy + oz * dz);
    const float delta = b * b - 4.0f * a * c;
    const float sq = sqrtf(delta > 0.0f ? delta : 1.0f);
    const float t_hit = __fdividef(-b + sq, 2.0f * a);
    const bool valid = (delta > 0.0f) && (t_hit >= 0.0f);

    const float hx = ox + dx * t_hit;
    const float hy = oy + dy * t_hit;
    const float hz = oz + dz * t_hit;

    // iy = (H/2)*(atan2/pi) + (H-1)/2 ;  ix = (W/pi)*acos(yc) - 0.5
    const float iy = atan2_fast(hx, -hz) * ((float)ENV_H * 0.5f / PI_F)
                   + ((float)ENV_H - 1.0f) * 0.5f;
    const float yc = fminf(fmaxf(hy, -1.0f + 1e-6f), 1.0f - 1e-6f);
    const float ix = acos_fast(yc) * ((float)ENV_W / PI_F) - 0.5f;

    const float fx0 = floorf(ix);
    const float fy0 = floorf(iy);

    RayPre r;
    r.t_hit = t_hit;
    r.valid = valid;
    r.wx1 = ix - fx0;
    r.wy1 = iy - fy0;
    r.x0 = (int)fx0;
    r.y0 = (int)fy0;
    return r;
}

__device__ __forceinline__ RayOut ray_gather(const RayPre& r, const float* s_env)
{
    const int   xs[2]  = {r.x0, r.x0 + 1};
    const int   ys[2]  = {r.y0, r.y0 + 1};
    const float wxs[2] = {1.0f - r.wx1, r.wx1};
    const float wys[2] = {1.0f - r.wy1, r.wy1};

    float acc0 = 0.0f, acc1 = 0.0f, acc2 = 0.0f;
#pragma unroll
    for (int jy = 0; jy < 2; jy++) {
#pragma unroll
        for (int jx = 0; jx < 2; jx++) {
            const int xcc = xs[jx];
            const int ycc = ys[jy];
            const bool inb = (xcc >= 0) && (xcc <= ENV_W - 1) &&
                             (ycc >= 0) && (ycc <= ENV_H - 1);
            const float w = wxs[jx] * wys[jy] * (inb ? 1.0f : 0.0f);
            const int xi = min(max(xcc, 0), ENV_W - 1);
            const int yi = min(max(ycc, 0), ENV_H - 1);
            const int base = yi * ENV_W + xi;
            acc0 = fmaf(w, s_env[base],               acc0);
            acc1 = fmaf(w, s_env[ENV_HW + base],      acc1);
            acc2 = fmaf(w, s_env[2 * ENV_HW + base],  acc2);
        }
    }

    const float st = SIGMA_MAJORANT * r.t_hit;
    RayOut o;
    o.v0 = r.valid ? __expf(acc0 - st) : 0.0f;
    o.v1 = r.valid ? __expf(acc1 - st) : 0.0f;
    o.v2 = r.valid ? __expf(acc2 - st) : 0.0f;
    return o;
}

__global__ void __launch_bounds__(THREADS)
nerf_env_kernel(const float* __restrict__ rays_o,
                const float* __restrict__ rays_d,
                const float* __restrict__ env,
                float* __restrict__ out,
                int N)
{
    __shared__ float s_env[ENV_ELEMS];

    const int t = threadIdx.x;
    const int base_ray = blockIdx.x * (THREADS * RAYS_PER_THREAD) + t;
    const int i0 = base_ray;                 // ray A
    const int i1 = base_ray + THREADS;       // ray B
    const bool a0 = (i0 < N);
    const bool a1 = (i1 < N);

    // issue env preload (registers; commits after the ray math)
    const float4* __restrict__ env4 = (const float4*)env;
    float4 e[F4_PER_THREAD];
#pragma unroll
    for (int k = 0; k < F4_PER_THREAD; k++)
        e[k] = env4[t + k * THREADS];

    // two independent ray pipelines (ILP=2)
    RayPre r0 = ray_pre(rays_o, rays_d, a0 ? i0 : 0);
    RayPre r1 = ray_pre(rays_o, rays_d, a1 ? i1 : 0);

    // commit env to smem, sync
    float4* s_env4 = (float4*)s_env;
#pragma unroll
    for (int k = 0; k < F4_PER_THREAD; k++)
        s_env4[t + k * THREADS] = e[k];
    __syncthreads();

    RayOut o0 = ray_gather(r0, s_env);
    RayOut o1 = ray_gather(r1, s_env);

    if (a0) {
        out[3 * i0 + 0] = o0.v0;
        out[3 * i0 + 1] = o0.v1;
        out[3 * i0 + 2] = o0.v2;
    }
    if (a1) {
        out[3 * i1 + 0] = o1.v0;
        out[3 * i1 + 1] = o1.v1;
        out[3 * i1 + 2] = o1.v2;
    }
}

extern "C" void kernel_launch(void* const* d_in, const int* in_sizes, int n_in,
                              void* d_out, int out_size)
{
    const float* rays_o = (const float*)d_in[0];
    const float* rays_d = (const float*)d_in[1];
    const float* env    = (const float*)d_in[2];
    float* out = (float*)d_out;

    const int N = in_sizes[0] / 3;
    const int per_block = THREADS * RAYS_PER_THREAD;
    const int blocks = (N + per_block - 1) / per_block;
    nerf_env_kernel<<<blocks, THREADS>>>(rays_o, rays_d, env, out, N);
}

// round 12
// speedup vs baseline: 1.1813x; 1.1813x over previous
#include <cuda_runtime.h>
#include <cuda_bf16.h>
#include <math.h>
#include <cstdint>

// NeRFRenderer null-scattering marcher (max_depths=1): all tot replicas of a
// ray are identical -> single per-ray eval: ray-sphere hit, equirect env-map
// bilinear sample, attenuate.
//
// inputs: d_in[0] rays_o f32[N,3], d_in[1] rays_d f32[N,3],
//         d_in[2] env_map f32[1,3,16,32], d_in[3..4] step counts (cancel).
// output: f32 [N,3]
//
// R11: single-warp CTAs (512 CTAs x 32 threads). Each warp stages the full
// 6KB env map itself (12 float4/lane) so there is NO block barrier — the
// env wait is a pure in-warp data dependency (+__syncwarp), removing the
// cross-warp arrival skew that the 64-thread CTA's __syncthreads exposed.
// ~3.5 CTAs/SM keep pipelines overlapped. Otherwise identical to the R6
// champion (register-staged preload overlapping the ray math).

#define ENV_H 16
#define ENV_W 32
#define ENV_HW (ENV_H * ENV_W)
#define ENV_ELEMS (3 * ENV_HW)              // 1536 floats = 384 float4
#define SIGMA_MAJORANT 0.1f
#define PI_F 3.14159265358979323846f
#define THREADS 32
#define F4_PER_THREAD (ENV_ELEMS / 4 / THREADS)   // 12

// fast acos, max err ~6.7e-5 rad
__device__ __forceinline__ float acos_fast(float x) {
    float ax = fabsf(x);
    float r = sqrtf(1.0f - ax) *
              (1.5707288f + ax * (-0.2121144f + ax * (0.0742610f + ax * (-0.0187293f))));
    return x < 0.0f ? (PI_F - r) : r;
}

// atan on [0,1], max err ~1e-5 rad
__device__ __forceinline__ float atan_poly(float a) {
    float s = a * a;
    return a * (0.9998660f + s * (-0.3302995f + s * (0.1801410f +
               s * (-0.0851330f + s * 0.0208351f))));
}

// fast atan2 (returns 0 at (0,0), matching nan_to_num in the reference)
__device__ __forceinline__ float atan2_fast(float y, float x) {
    float ay = fabsf(y), ax = fabsf(x);
    bool swap = ay > ax;
    float num = swap ? ax : ay;
    float den = swap ? ay : ax;
    den = fmaxf(den, 1e-30f);
    float r = atan_poly(__fdividef(num, den));
    if (swap) r = 1.57079632679f - r;
    if (x < 0.0f) r = PI_F - r;
    return y < 0.0f ? -r : r;
}

__global__ void __launch_bounds__(THREADS)
nerf_env_kernel(const float* __restrict__ rays_o,
                const float* __restrict__ rays_d,
                const float* __restrict__ env,
                float* __restrict__ out,
                int N)
{
    __shared__ float s_env[ENV_ELEMS];

    const int i = blockIdx.x * THREADS + threadIdx.x;
    const bool active = (i < N);
    const int ii = active ? i : 0;
    const int t = threadIdx.x;

    // issue ray loads first
    const float ox = rays_o[3 * ii + 0];
    const float oy = rays_o[3 * ii + 1];
    const float oz = rays_o[3 * ii + 2];
    const float dx = rays_d[3 * ii + 0];
    const float dy = rays_d[3 * ii + 1];
    const float dz = rays_d[3 * ii + 2];

    // issue env preload: 384 float4 total, 12 per lane (warp-private staging)
    const float4* __restrict__ env4 = (const float4*)env;
    float4 e[F4_PER_THREAD];
#pragma unroll
    for (int k = 0; k < F4_PER_THREAD; k++)
        e[k] = env4[t + k * THREADS];

    // ---- env-independent math (overlaps the load latency above) ----
    const float a = dx * dx + dy * dy + dz * dz;
    const float c = ox * ox + oy * oy + oz * oz - 1.0f;
    const float b = 2.0f * (ox * dx + oy * dy + oz * dz);
    const float delta = b * b - 4.0f * a * c;
    const float sq = sqrtf(delta > 0.0f ? delta : 1.0f);
    const float t_hit = __fdividef(-b + sq, 2.0f * a);
    const bool valid = (delta > 0.0f) && (t_hit >= 0.0f);

    const float hx = ox + dx * t_hit;
    const float hy = oy + dy * t_hit;
    const float hz = oz + dz * t_hit;

    // grid-sample coords, affine folded in:
    //   iy = (H/2)*(atan2/pi) + (H-1)/2 ;  ix = (W/pi)*acos(yc) - 0.5
    const float iy = atan2_fast(hx, -hz) * ((float)ENV_H * 0.5f / PI_F)
                   + ((float)ENV_H - 1.0f) * 0.5f;
    const float yc = fminf(fmaxf(hy, -1.0f + 1e-6f), 1.0f - 1e-6f);
    const float ix = acos_fast(yc) * ((float)ENV_W / PI_F) - 0.5f;

    const float fx0 = floorf(ix);
    const float fy0 = floorf(iy);
    const float wx1 = ix - fx0;
    const float wy1 = iy - fy0;
    const int x0 = (int)fx0;
    const int y0 = (int)fy0;

    const int   xs[2]  = {x0, x0 + 1};
    const int   ys[2]  = {y0, y0 + 1};
    const float wxs[2] = {1.0f - wx1, wx1};
    const float wys[2] = {1.0f - wy1, wy1};

    // ---- commit env to smem (in-warp only), gather ----
    float4* s_env4 = (float4*)s_env;
#pragma unroll
    for (int k = 0; k < F4_PER_THREAD; k++)
        s_env4[t + k * THREADS] = e[k];
    __syncwarp();

    float acc0 = 0.0f, acc1 = 0.0f, acc2 = 0.0f;
#pragma unroll
    for (int jy = 0; jy < 2; jy++) {
#pragma unroll
        for (int jx = 0; jx < 2; jx++) {
            const int xcc = xs[jx];
            const int ycc = ys[jy];
            const bool inb = (xcc >= 0) && (xcc <= ENV_W - 1) &&
                             (ycc >= 0) && (ycc <= ENV_H - 1);
            const float w = wxs[jx] * wys[jy] * (inb ? 1.0f : 0.0f);
            const int xi = min(max(xcc, 0), ENV_W - 1);
            const int yi = min(max(ycc, 0), ENV_H - 1);
            const int base = yi * ENV_W + xi;
            acc0 = fmaf(w, s_env[base],               acc0);
            acc1 = fmaf(w, s_env[ENV_HW + base],      acc1);
            acc2 = fmaf(w, s_env[2 * ENV_HW + base],  acc2);
        }
    }

    if (active) {
        const float st = SIGMA_MAJORANT * t_hit;
        out[3 * i + 0] = valid ? __expf(acc0 - st) : 0.0f;
        out[3 * i + 1] = valid ? __expf(acc1 - st) : 0.0f;
        out[3 * i + 2] = valid ? __expf(acc2 - st) : 0.0f;
    }
}

extern "C" void kernel_launch(void* const* d_in, const int* in_sizes, int n_in,
                              void* d_out, int out_size)
{
    const float* rays_o = (const float*)d_in[0];
    const float* rays_d = (const float*)d_in[1];
    const float* env    = (const float*)d_in[2];
    float* out = (float*)d_out;

    const int N = in_sizes[0] / 3;
    const int blocks = (N + THREADS - 1) / THREADS;
    nerf_env_kernel<<<blocks, THREADS>>>(rays_o, rays_d, env, out, N);
}